// round 7
// baseline (speedup 1.0000x reference)
#include <cuda_runtime.h>
#include <math.h>
#include <stdint.h>

#define PRE    64
#define BATCH  1024
#define NNB    256
#define NPAIR  (NNB / 2)     // 128 f32x2 neighbour pairs per batch
#define MASSF  60.0f
#define BPB    4             // batches per block
#define NBLK   (BATCH / BPB) // 256 blocks
#define NTHR   512           // 128 threads per batch: 4 c-lanes x 32 t-pairs

// accumulators: [0] = 4 * sum energy_norm / MASS, [1] = sum squared error
__device__ float    g_acc[2] = {0.0f, 0.0f};
__device__ unsigned g_cnt    = 0;

// ---------------- packed f32x2 helpers (Blackwell) ----------------
static __device__ __forceinline__ uint64_t fpack(float a, float b) {
    uint64_t r; asm("mov.b64 %0,{%1,%2};" : "=l"(r) : "f"(a), "f"(b)); return r;
}
static __device__ __forceinline__ void funpack(uint64_t p, float& a, float& b) {
    asm("mov.b64 {%0,%1},%2;" : "=f"(a), "=f"(b) : "l"(p));
}
static __device__ __forceinline__ uint64_t padd(uint64_t a, uint64_t b) {
    uint64_t r; asm("add.rn.f32x2 %0,%1,%2;" : "=l"(r) : "l"(a), "l"(b)); return r;
}
static __device__ __forceinline__ uint64_t pmul(uint64_t a, uint64_t b) {
    uint64_t r; asm("mul.rn.f32x2 %0,%1,%2;" : "=l"(r) : "l"(a), "l"(b)); return r;
}
static __device__ __forceinline__ uint64_t pfma(uint64_t a, uint64_t b, uint64_t c) {
    uint64_t r; asm("fma.rn.f32x2 %0,%1,%2,%3;" : "=l"(r) : "l"(a), "l"(b), "l"(c)); return r;
}
static __device__ __forceinline__ uint64_t prsqrt(uint64_t m) {
    float a, b; funpack(m, a, b);
    float ra, rb;
    asm("rsqrt.approx.f32 %0,%1;" : "=f"(ra) : "f"(a));
    asm("rsqrt.approx.f32 %0,%1;" : "=f"(rb) : "f"(b));
    return fpack(ra, rb);
}

// ---------------------------------------------------------------------------
// Fused kernel, 256 blocks x 512 threads, 4 batches per block, <=128 regs.
// Thread: bb = tid>>7 (batch in block, warp-uniform), r = tid&127,
// c = r&3 (pair lane), tg = r>>2 -> timesteps {2tg, 2tg+1}.
// Pairs p = 4i+c, i = 0..31; software-pipelined LDS prefetch of record i+1.
// Per (t, pair): dx=px-nx; dy=py-ny; r2=dx^2+dy^2; x_=ca*dx+sa*dy; x2=x_^2;
// y2=r2-x2; den=x2^3+y2^3+6; w=rsqrt(den^2*r2); ex+=w*dx; ey+=w*dy.
// (MASS and the atan2 trig/signs cancel into the finalize constant.)
// ---------------------------------------------------------------------------
__global__ __launch_bounds__(NTHR, 2)
void fused_kernel(const float* __restrict__ out,   // (PRE, BATCH, 2)
                  const float* __restrict__ tgt,   // (PRE, BATCH, 2)
                  const float* __restrict__ nb,    // (BATCH, NNB, 5)
                  float* __restrict__ dst)
{
    __shared__ ulonglong2 s_xy[BPB][NPAIR]; // {fpack(-nx0,-nx1), fpack(-ny0,-ny1)}
    __shared__ ulonglong2 s_cs[BPB][NPAIR]; // {fpack( ca0, ca1), fpack( sa0, sa1)}
    __shared__ float s_red[32];

    const int tid = threadIdx.x;
    const int b0  = blockIdx.x * BPB;

    const int bb = tid >> 7;          // batch in block (warp-uniform)
    const int r  = tid & 127;
    const int c  = r & 3;             // pair-chunk lane
    const int tg = r >> 2;            // timestep pair 0..31
    const int b  = b0 + bb;

    // ---- point loads first: overlap their latency with staging ----
    const float2 pa = ((const float2*)out)[(size_t)(2 * tg)     * BATCH + b];
    const float2 pb = ((const float2*)out)[(size_t)(2 * tg + 1) * BATCH + b];

    // ---- MSE slice: one float per thread; 256*512 = 131072 = PRE*BATCH*2 ----
    float msum;
    {
        const int g = blockIdx.x * NTHR + tid;
        const float d = out[g] - tgt[g];
        msum = d * d;
    }

    // ---- stage neighbours: 512 pair-records, one per thread ----
    {
        const int sb = tid >> 7;
        const int p  = tid & (NPAIR - 1);
        // record = 2 neighbours x 5 floats = 40 bytes, float2-aligned
        const float2* q2 = (const float2*)(nb + ((size_t)(b0 + sb) * NNB + 2 * p) * 5);
        const float2 r0 = q2[0];   // nx0 ny0
        const float2 r1 = q2[1];   // z0  w0
        const float2 r2v = q2[2];  // a0  nx1
        const float2 r3 = q2[3];   // ny1 z1
        const float2 r4 = q2[4];   // w1  a1
        const float nx0 = r0.x, ny0 = r0.y, a0 = r2v.x;
        const float nx1 = r2v.y, ny1 = r3.x, a1 = r4.y;
        (void)r1;
        float sa0, ca0, sa1, ca1;
        __sincosf(a0, &sa0, &ca0);
        __sincosf(a1, &sa1, &ca1);
        ulonglong2 xy, cs;
        xy.x = fpack(-nx0, -nx1);
        xy.y = fpack(-ny0, -ny1);
        cs.x = fpack( ca0,  ca1);
        cs.y = fpack( sa0,  sa1);
        s_xy[sb][p] = xy;
        s_cs[sb][p] = cs;
    }
    __syncthreads();

    const uint64_t pxa = fpack(pa.x, pa.x), pya = fpack(pa.y, pa.y);
    const uint64_t pxb = fpack(pb.x, pb.x), pyb = fpack(pb.y, pb.y);
    const uint64_t six2  = fpack(6.0f, 6.0f);
    const uint64_t mone2 = fpack(-1.0f, -1.0f);

    uint64_t axa = 0ull, aya = 0ull;  // (+0.0f, +0.0f)
    uint64_t axb = 0ull, ayb = 0ull;

    // software-pipelined: prefetch record i+1 while computing record i
    ulonglong2 xy = s_xy[bb][c];
    ulonglong2 cs = s_cs[bb][c];

    #pragma unroll
    for (int i = 0; i < NPAIR / 4; ++i) {
        const ulonglong2 xy_c = xy;
        const ulonglong2 cs_c = cs;
        if (i + 1 < NPAIR / 4) {
            const int pn = ((i + 1) << 2) | c;
            xy = s_xy[bb][pn];
            cs = s_cs[bb][pn];
        }

        {   // timestep 2*tg
            const uint64_t dx = padd(pxa, xy_c.x);
            const uint64_t dy = padd(pya, xy_c.y);
            const uint64_t r2 = pfma(dx, dx, pmul(dy, dy));
            const uint64_t x_ = pfma(cs_c.x, dx, pmul(cs_c.y, dy));
            const uint64_t x2 = pmul(x_, x_);
            const uint64_t y2 = pfma(x2, mone2, r2);
            const uint64_t den = pfma(pmul(x2, x2), x2,
                                 pfma(pmul(y2, y2), y2, six2));
            const uint64_t w = prsqrt(pmul(pmul(den, den), r2));
            axa = pfma(w, dx, axa);
            aya = pfma(w, dy, aya);
        }
        {   // timestep 2*tg + 1
            const uint64_t dx = padd(pxb, xy_c.x);
            const uint64_t dy = padd(pyb, xy_c.y);
            const uint64_t r2 = pfma(dx, dx, pmul(dy, dy));
            const uint64_t x_ = pfma(cs_c.x, dx, pmul(cs_c.y, dy));
            const uint64_t x2 = pmul(x_, x_);
            const uint64_t y2 = pfma(x2, mone2, r2);
            const uint64_t den = pfma(pmul(x2, x2), x2,
                                 pfma(pmul(y2, y2), y2, six2));
            const uint64_t w = prsqrt(pmul(pmul(den, den), r2));
            axb = pfma(w, dx, axb);
            ayb = pfma(w, dy, ayb);
        }
    }

    // combine packed halves, reduce over the 4 c-lanes
    float t0, t1;
    funpack(axa, t0, t1); float exa = t0 + t1;
    funpack(aya, t0, t1); float eya = t0 + t1;
    funpack(axb, t0, t1); float exb = t0 + t1;
    funpack(ayb, t0, t1); float eyb = t0 + t1;
    #pragma unroll
    for (int o = 1; o <= 2; o <<= 1) {
        exa += __shfl_xor_sync(0xffffffffu, exa, o);
        eya += __shfl_xor_sync(0xffffffffu, eya, o);
        exb += __shfl_xor_sync(0xffffffffu, exb, o);
        eyb += __shfl_xor_sync(0xffffffffu, eyb, o);
    }

    // identical on 4 c-lanes -> warp sum overcounts 4x (folded in finalize)
    float v = sqrtf(fmaf(exa, exa, eya * eya))
            + sqrtf(fmaf(exb, exb, eyb * eyb));

    #pragma unroll
    for (int o = 16; o; o >>= 1) {
        v    += __shfl_xor_sync(0xffffffffu, v,    o);
        msum += __shfl_xor_sync(0xffffffffu, msum, o);
    }
    if ((tid & 31) == 0) {
        s_red[(tid >> 5) * 2 + 0] = v;
        s_red[(tid >> 5) * 2 + 1] = msum;
    }
    __syncthreads();

    if (tid == 0) {
        float fv = 0.0f, fm = 0.0f;
        #pragma unroll
        for (int w16 = 0; w16 < 16; ++w16) {
            fv += s_red[w16 * 2 + 0];
            fm += s_red[w16 * 2 + 1];
        }
        atomicAdd(&g_acc[0], fv);
        atomicAdd(&g_acc[1], fm);
        __threadfence();
        const unsigned rr = atomicAdd(&g_cnt, 1u);
        if (rr == (unsigned)(NBLK - 1)) {
            __threadfence();
            const float fe = *((volatile float*)&g_acc[0]);   // 4x, /MASS
            const float mm = *((volatile float*)&g_acc[1]);
            dst[0] = mm * (1.0f / (float)(PRE * BATCH * 2))
                   + fe * (MASSF / (4.0f * (float)(PRE * BATCH)));
            g_acc[0] = 0.0f;
            g_acc[1] = 0.0f;
            __threadfence();
            g_cnt = 0;
        }
    }
}

extern "C" void kernel_launch(void* const* d_in, const int* in_sizes, int n_in,
                              void* d_out, int out_size)
{
    const float* output     = (const float*)d_in[0];   // (64, 1024, 2)
    const float* target     = (const float*)d_in[1];   // (64, 1024, 2)
    const float* neighbours = (const float*)d_in[2];   // (1024, 256, 5)
    float* dst = (float*)d_out;

    fused_kernel<<<NBLK, NTHR>>>(output, target, neighbours, dst);
}

// round 8
// speedup vs baseline: 1.0031x; 1.0031x over previous
#include <cuda_runtime.h>
#include <math.h>
#include <stdint.h>

#define PRE    64
#define BATCH  1024
#define NNB    256
#define MASSF  60.0f
#define NBLK   BATCH         // 1024 blocks, one batch each
#define NTHR   256           // 8 nb-lanes x 32 timestep-pairs

// accumulators: [0] = 8 * sum energy_norm / MASS, [1] = sum squared error
__device__ float    g_acc[2] = {0.0f, 0.0f};
__device__ unsigned g_cnt    = 0;

static __device__ __forceinline__ float frsqrt(float x) {
    float r; asm("rsqrt.approx.f32 %0,%1;" : "=f"(r) : "f"(x)); return r;
}

// ---------------------------------------------------------------------------
// Fused kernel, 1024 blocks x 256 threads, one batch per block.
// Thread: c = tid&7 (neighbour lane), tg = tid>>3 -> timesteps {2tg, 2tg+1}.
// Neighbour j = 8i+c (i = 0..31); one float4 LDS per neighbour feeds BOTH
// timesteps. PURE SCALAR fp32 (f32x2 is sm_103a-only; emulated on sm_100a).
// Per (t, neighbour): 16 FFMA-pipe ops + 1 MUFU.RSQ:
//   dx=px-nx; dy=py-ny; r2=dx^2+dy^2; x_=ca*dx+sa*dy; x2=x_^2; y2=r2-x2;
//   den=x2^3+y2^3+6; w=rsqrt(den^2*r2); ex+=w*dx; ey+=w*dy
// (MASS and the atan2 trig/signs cancel into the finalize constant.)
// v identical across the 8 c-lanes -> warp-sum overcounts 8x; folded into
// the finalize constant.
// ---------------------------------------------------------------------------
__global__ __launch_bounds__(NTHR, 4)
void fused_kernel(const float* __restrict__ out,   // (PRE, BATCH, 2)
                  const float* __restrict__ tgt,   // (PRE, BATCH, 2)
                  const float* __restrict__ nb,    // (BATCH, NNB, 5)
                  float* __restrict__ dst)
{
    __shared__ float4 s_nb[NNB];      // {-nx, -ny, ca, sa} per neighbour
    __shared__ float  s_red[16];

    const int tid = threadIdx.x;
    const int b   = blockIdx.x;

    const int c  = tid & 7;           // neighbour lane
    const int tg = tid >> 3;          // timestep pair 0..31

    // ---- point loads early: overlap latency with staging ----
    const float2 pa = ((const float2*)out)[(size_t)(2 * tg)     * BATCH + b];
    const float2 pb = ((const float2*)out)[(size_t)(2 * tg + 1) * BATCH + b];

    // ---- MSE slice: first 131072 of 262144 global threads ----
    float msum = 0.0f;
    {
        const int g = b * NTHR + tid;
        if (g < PRE * BATCH * 2) {
            const float d = out[g] - tgt[g];
            msum = d * d;
        }
    }

    // ---- stage neighbours: one per thread, sincos precomputed ----
    {
        const float* q = nb + ((size_t)b * NNB + tid) * 5;
        const float nx = q[0];
        const float ny = q[1];
        const float an = q[4];
        float sa, ca;
        __sincosf(an, &sa, &ca);
        s_nb[tid] = make_float4(-nx, -ny, ca, sa);
    }
    __syncthreads();

    const float pxa = pa.x, pya = pa.y;
    const float pxb = pb.x, pyb = pb.y;

    float exa = 0.0f, eya = 0.0f;
    float exb = 0.0f, eyb = 0.0f;

    #pragma unroll 8
    for (int i = 0; i < NNB / 8; ++i) {
        const float4 nr = s_nb[(i << 3) | c];   // {-nx, -ny, ca, sa}

        {   // timestep 2*tg
            const float dx = pxa + nr.x;
            const float dy = pya + nr.y;
            const float r2 = fmaf(dx, dx, dy * dy);
            const float x_ = fmaf(nr.z, dx, nr.w * dy);
            const float x2 = x_ * x_;
            const float y2 = r2 - x2;
            const float x4 = x2 * x2;
            const float y4 = y2 * y2;
            const float den = fmaf(x4, x2, fmaf(y4, y2, 6.0f));
            const float w = frsqrt(den * den * r2);
            exa = fmaf(w, dx, exa);
            eya = fmaf(w, dy, eya);
        }
        {   // timestep 2*tg + 1
            const float dx = pxb + nr.x;
            const float dy = pyb + nr.y;
            const float r2 = fmaf(dx, dx, dy * dy);
            const float x_ = fmaf(nr.z, dx, nr.w * dy);
            const float x2 = x_ * x_;
            const float y2 = r2 - x2;
            const float x4 = x2 * x2;
            const float y4 = y2 * y2;
            const float den = fmaf(x4, x2, fmaf(y4, y2, 6.0f));
            const float w = frsqrt(den * den * r2);
            exb = fmaf(w, dx, exb);
            eyb = fmaf(w, dy, eyb);
        }
    }

    // reduce partial sums over the 8 c-lanes (lanes differ in bits [0:3))
    #pragma unroll
    for (int o = 1; o <= 4; o <<= 1) {
        exa += __shfl_xor_sync(0xffffffffu, exa, o);
        eya += __shfl_xor_sync(0xffffffffu, eya, o);
        exb += __shfl_xor_sync(0xffffffffu, exb, o);
        eyb += __shfl_xor_sync(0xffffffffu, eyb, o);
    }

    // identical on 8 c-lanes -> warp sum overcounts 8x (folded in finalize)
    float v = sqrtf(fmaf(exa, exa, eya * eya))
            + sqrtf(fmaf(exb, exb, eyb * eyb));

    #pragma unroll
    for (int o = 16; o; o >>= 1) {
        v    += __shfl_xor_sync(0xffffffffu, v,    o);
        msum += __shfl_xor_sync(0xffffffffu, msum, o);
    }
    if ((tid & 31) == 0) {
        s_red[(tid >> 5) * 2 + 0] = v;
        s_red[(tid >> 5) * 2 + 1] = msum;
    }
    __syncthreads();

    if (tid == 0) {
        float fv = 0.0f, fm = 0.0f;
        #pragma unroll
        for (int w8 = 0; w8 < 8; ++w8) {
            fv += s_red[w8 * 2 + 0];
            fm += s_red[w8 * 2 + 1];
        }
        atomicAdd(&g_acc[0], fv);
        atomicAdd(&g_acc[1], fm);
        __threadfence();
        const unsigned rr = atomicAdd(&g_cnt, 1u);
        if (rr == (unsigned)(NBLK - 1)) {
            __threadfence();
            const float fe = *((volatile float*)&g_acc[0]);   // 8x, /MASS
            const float mm = *((volatile float*)&g_acc[1]);
            dst[0] = mm * (1.0f / (float)(PRE * BATCH * 2))
                   + fe * (MASSF / (8.0f * (float)(PRE * BATCH)));
            g_acc[0] = 0.0f;
            g_acc[1] = 0.0f;
            __threadfence();
            g_cnt = 0;
        }
    }
}

extern "C" void kernel_launch(void* const* d_in, const int* in_sizes, int n_in,
                              void* d_out, int out_size)
{
    const float* output     = (const float*)d_in[0];   // (64, 1024, 2)
    const float* target     = (const float*)d_in[1];   // (64, 1024, 2)
    const float* neighbours = (const float*)d_in[2];   // (1024, 256, 5)
    float* dst = (float*)d_out;

    fused_kernel<<<NBLK, NTHR>>>(output, target, neighbours, dst);
}

// round 10
// speedup vs baseline: 1.0063x; 1.0031x over previous
#include <cuda_runtime.h>
#include <cuda_fp16.h>
#include <math.h>
#include <stdint.h>

#define PRE    64
#define BATCH  1024
#define NNB    256
#define MASSF  60.0f
#define NBLK   BATCH         // 1024 blocks, one batch each
#define NTHR   256           // 8 nb-lanes x 32 timestep-pairs

// accumulators: [0] = 8(lanes) * 64(den-scale) * sum energy_norm / MASS
//               [1] = sum squared error
__device__ float    g_acc[2] = {0.0f, 0.0f};
__device__ unsigned g_cnt    = 0;

struct __align__(16) NbRec {      // 16B -> one LDS.128
    float   mnx;                  // -nx (fp32)
    float   mny;                  // -ny (fp32)
    __half2 ca2;                  // {ca/2, ca/2}
    __half2 sa2;                  // {sa/2, sa/2}
};

// ---------------------------------------------------------------------------
// Fused kernel, 1024 blocks x 256 threads, one batch per block.
// Thread: c = tid&7 (neighbour lane), tg = tid>>3; timesteps {2tg, 2tg+1}
// ride the two half2 lanes THROUGH THE POLYNOMIAL ONLY.
// Per neighbour (= 2 timesteps): 20 fma-pipe ops + 4 CVT + 1 MUFU + 1 LDS:
//   fp32: dx,dy per timestep (exact small deltas)            [4 FADD]
//   pack (dxa,dxb),(dya,dyb) -> half2                         [2 CVT]
//   fp16: r2 = dx^2+dy^2; x' = (ca*dx+sa*dy)/2; x2'=x'^2;
//         y2' = r2/4 - x2'; den'' = x2'^3+y2'^3+6/64 (= den/64);
//         m = den''^2 * r2 + 2^-20;  w = rsqrt(m) (= 64/(den*r))
//         [12 fp16 fma-pipe + 1 MUFU]
//   unpack w -> fp32                                          [2 CVT]
//   fp32: ex += w*dx, ey += w*dy                              [4 FFMA]
// den''^2 overflow (den > 16377, P~4e-4) -> w=0, bias ~6e-6. eps=2^-20
// (fp16 subnormal) only guards exact r2=0 -> NaN.
// (MASS, the /64 scale, atan2 trig and signs all fold into finalize.)
// ---------------------------------------------------------------------------
__global__ __launch_bounds__(NTHR, 4)
void fused_kernel(const float* __restrict__ out,   // (PRE, BATCH, 2)
                  const float* __restrict__ tgt,   // (PRE, BATCH, 2)
                  const float* __restrict__ nb,    // (BATCH, NNB, 5)
                  float* __restrict__ dst)
{
    __shared__ NbRec s_nb[NNB];
    __shared__ float s_red[16];

    const int tid = threadIdx.x;
    const int b   = blockIdx.x;

    const int c  = tid & 7;           // neighbour lane
    const int tg = tid >> 3;          // timestep pair 0..31

    // ---- point loads early: overlap latency with staging ----
    const float2 pa = ((const float2*)out)[(size_t)(2 * tg)     * BATCH + b];
    const float2 pb = ((const float2*)out)[(size_t)(2 * tg + 1) * BATCH + b];

    // ---- MSE slice (fp32): first 131072 of 262144 global threads ----
    float msum = 0.0f;
    {
        const int g = b * NTHR + tid;
        if (g < PRE * BATCH * 2) {
            const float d = out[g] - tgt[g];
            msum = d * d;
        }
    }

    // ---- stage neighbours: one per thread; sincos fp32, /2 fold ----
    {
        const float* q = nb + ((size_t)b * NNB + tid) * 5;
        const float nx = q[0];
        const float ny = q[1];
        const float an = q[4];
        float sa, ca;
        __sincosf(an, &sa, &ca);
        NbRec rec;
        rec.mnx = -nx;
        rec.mny = -ny;
        rec.ca2 = __float2half2_rn(ca * 0.5f);
        rec.sa2 = __float2half2_rn(sa * 0.5f);
        s_nb[tid] = rec;
    }
    __syncthreads();

    const float pxa = pa.x, pya = pa.y;
    const float pxb = pb.x, pyb = pb.y;

    const __half2 c025 = __float2half2_rn(0.25f);
    const __half2 cden = __float2half2_rn(0.09375f);        // 6/64
    const __half2 epsm = __float2half2_rn(9.5367432e-7f);   // 2^-20 (subnormal)

    float exa = 0.0f, eya = 0.0f;
    float exb = 0.0f, eyb = 0.0f;

    #pragma unroll 8
    for (int i = 0; i < NNB / 8; ++i) {
        const NbRec nr = s_nb[(i << 3) | c];

        // fp32 deltas (exact where it matters)
        const float dxa = pxa + nr.mnx;
        const float dya = pya + nr.mny;
        const float dxb = pxb + nr.mnx;
        const float dyb = pyb + nr.mny;

        // fp16 polynomial, timesteps in the two half2 lanes
        const __half2 dx2 = __floats2half2_rn(dxa, dxb);
        const __half2 dy2 = __floats2half2_rn(dya, dyb);
        const __half2 r2  = __hfma2(dx2, dx2, __hmul2(dy2, dy2));
        const __half2 x_  = __hfma2(nr.ca2, dx2, __hmul2(nr.sa2, dy2)); // x/2
        const __half2 x2  = __hmul2(x_, x_);                            // x^2/4
        const __half2 y2  = __hfma2(r2, c025, __hneg2(x2));             // y^2/4
        const __half2 x4  = __hmul2(x2, x2);
        const __half2 y4  = __hmul2(y2, y2);
        const __half2 den = __hfma2(x4, x2, __hfma2(y4, y2, cden));     // den/64
        const __half2 ds2 = __hmul2(den, den);
        const __half2 m   = __hfma2(ds2, r2, epsm);
        const __half2 w2  = h2rsqrt(m);                                 // 64/(den*r)

        // fp32 accumulation
        const float wa = __low2float(w2);
        const float wb = __high2float(w2);
        exa = fmaf(wa, dxa, exa);
        eya = fmaf(wa, dya, eya);
        exb = fmaf(wb, dxb, exb);
        eyb = fmaf(wb, dyb, eyb);
    }

    // reduce partial sums over the 8 c-lanes (bits [0:3) of lane id)
    #pragma unroll
    for (int o = 1; o <= 4; o <<= 1) {
        exa += __shfl_xor_sync(0xffffffffu, exa, o);
        eya += __shfl_xor_sync(0xffffffffu, eya, o);
        exb += __shfl_xor_sync(0xffffffffu, exb, o);
        eyb += __shfl_xor_sync(0xffffffffu, eyb, o);
    }

    // identical on 8 c-lanes -> warp sum overcounts 8x (folded in finalize)
    float v = sqrtf(fmaf(exa, exa, eya * eya))
            + sqrtf(fmaf(exb, exb, eyb * eyb));

    #pragma unroll
    for (int o = 16; o; o >>= 1) {
        v    += __shfl_xor_sync(0xffffffffu, v,    o);
        msum += __shfl_xor_sync(0xffffffffu, msum, o);
    }
    if ((tid & 31) == 0) {
        s_red[(tid >> 5) * 2 + 0] = v;
        s_red[(tid >> 5) * 2 + 1] = msum;
    }
    __syncthreads();

    if (tid == 0) {
        float fv = 0.0f, fm = 0.0f;
        #pragma unroll
        for (int w8 = 0; w8 < 8; ++w8) {
            fv += s_red[w8 * 2 + 0];
            fm += s_red[w8 * 2 + 1];
        }
        atomicAdd(&g_acc[0], fv);
        atomicAdd(&g_acc[1], fm);
        __threadfence();
        const unsigned rr = atomicAdd(&g_cnt, 1u);
        if (rr == (unsigned)(NBLK - 1)) {
            __threadfence();
            const float fe = *((volatile float*)&g_acc[0]);
            const float mm = *((volatile float*)&g_acc[1]);
            // fe = 8(lanes) * 64(w-scale: w = 64/(den r)) * sum(v)/MASS
            dst[0] = mm * (1.0f / (float)(PRE * BATCH * 2))
                   + fe * (MASSF / (512.0f * (float)(PRE * BATCH)));
            g_acc[0] = 0.0f;
            g_acc[1] = 0.0f;
            __threadfence();
            g_cnt = 0;
        }
    }
}

extern "C" void kernel_launch(void* const* d_in, const int* in_sizes, int n_in,
                              void* d_out, int out_size)
{
    const float* output     = (const float*)d_in[0];   // (64, 1024, 2)
    const float* target     = (const float*)d_in[1];   // (64, 1024, 2)
    const float* neighbours = (const float*)d_in[2];   // (1024, 256, 5)
    float* dst = (float*)d_out;

    fused_kernel<<<NBLK, NTHR>>>(output, target, neighbours, dst);
}